// round 12
// baseline (speedup 1.0000x reference)
#include <cuda_runtime.h>

#define TAILB 12.0f
#define MIN_BW 1e-6f
#define MIN_BH 1e-6f
#define MIN_DD 1e-6f

// layer index tables
__device__ __constant__ int MI0c[4] = {0, 1, 0, 2};
__device__ __constant__ int MI1c[4] = {2, 3, 1, 3};
__device__ __constant__ int II0c[4] = {1, 0, 2, 0};
__device__ __constant__ int II1c[4] = {3, 2, 3, 1};

__device__ __forceinline__ unsigned long long fma2(unsigned long long a,
                                                   unsigned long long b,
                                                   unsigned long long c) {
    unsigned long long d;
    asm("fma.rn.f32x2 %0, %1, %2, %3;" : "=l"(d) : "l"(a), "l"(b), "l"(c));
    return d;
}
__device__ __forceinline__ float lo32(unsigned long long a) {
    return __uint_as_float((unsigned)(a & 0xffffffffull));
}
__device__ __forceinline__ float hi32(unsigned long long a) {
    return __uint_as_float((unsigned)(a >> 32));
}
__device__ __forceinline__ float softplusf(float x) {
    return fmaxf(x, 0.0f) + log1pf(expf(-fabsf(x)));
}

// Shared memory (floats). 128 samples / block, 512 threads.
// h layout (4-k-contiguous, LDS.128): 32 rows of 4 samples, row stride 516
// (mod 32 = 4 => rows spread over 8 bank-quads; 4-wf floor loads, no extra
// conflicts). Element (s, k):
//   h[(s>>2)*516 + (k>>2)*16 + (s&3)*4 + (k&3)].
// pb (spline params, stride 50 => conflict-free spline reads) ALIASES h1.
#define OFF_H1   0        // 32*516 = 16512
#define OFF_PB   0        // aliases h1 (128*50 = 6400 <= 16512)
#define OFF_H2   16512    // 16512
#define OFF_W2   33024    // 16384
#define OFF_W3   49408    // 48*128 = 6144
#define OFF_W1   55552    // 384
#define OFF_B1   55936    // 128
#define OFF_B2   56064    // 128
#define OFF_B3   56192    // 48
#define OFF_XS   56240    // 512
#define OFF_CS   56752    // 128
#define OFF_LAD  56880    // 256
#define OFF_LDT  57136    // 128
#define SMEM_FLOATS 57264 // 229,056 bytes

__global__ __launch_bounds__(512, 1)
void rqs_fused_kernel(const float* __restrict__ inputs,
                      const float* __restrict__ cond,
                      const float* __restrict__ W1, const float* __restrict__ b1,
                      const float* __restrict__ W2, const float* __restrict__ b2,
                      const float* __restrict__ W3, const float* __restrict__ b3,
                      float* __restrict__ out, int B)
{
    extern __shared__ float sm[];
    float* h1  = sm + OFF_H1;
    float* h2  = sm + OFF_H2;
    float* sW2 = sm + OFF_W2;
    float* sW3 = sm + OFF_W3;
    float* sW1 = sm + OFF_W1;
    float* sb1 = sm + OFF_B1;
    float* sb2 = sm + OFF_B2;
    float* sb3 = sm + OFF_B3;
    float* xs  = sm + OFF_XS;
    float* cs  = sm + OFF_CS;
    float* pb  = sm + OFF_PB;
    float* lad = sm + OFF_LAD;
    float* ldt = sm + OFF_LDT;

    const int t = threadIdx.x;
    const int base = blockIdx.x * 128;

    xs[t] = inputs[base * 4 + t];
    if (t < 128) { cs[t] = cond[base + t]; ldt[t] = 0.0f; }

    const int q  = t & 31;   // sample row: samples 4q .. 4q+3
    const int g  = t >> 5;   // output group 0..15 (uniform per warp)

    #pragma unroll 1
    for (int l = 0; l < 4; l++) {
        __syncthreads();
        // ---- stage layer weights into smem ----
        {
            const float4* w2p = (const float4*)(W2 + l * 16384);
            float4* dW2 = (float4*)sW2;
            #pragma unroll
            for (int i = 0; i < 8; i++) dW2[t + i * 512] = w2p[t + i * 512];

            const float4* w3p = (const float4*)(W3 + l * 5888);
            float4* dW3 = (float4*)sW3;
            #pragma unroll
            for (int i = 0; i < 3; i++) {
                int idx = t + i * 512;
                if (idx < 1472) dW3[idx] = w3p[idx];
            }
            if (t < 64) dW3[1472 + t] = make_float4(0.f, 0.f, 0.f, 0.f);

            if (t < 96) ((float4*)sW1)[t] = ((const float4*)(W1 + l * 384))[t];
            if (t < 128) { sb1[t] = b1[l * 128 + t]; sb2[t] = b2[l * 128 + t]; }
            if (t < 48) sb3[t] = (t < 46) ? b3[l * 46 + t] : 0.0f;
        }
        __syncthreads();

        // ---- layer 1: h1 = relu([x_m0, x_m1, cond] @ W1^T + b1) ----
        // thread computes h-pair (2p, 2p+1) for sample s; STS.64 store.
        {
            const int mi0 = MI0c[l], mi1 = MI1c[l];
            #pragma unroll
            for (int i = 0; i < 16; i++) {
                int idx = t + i * 512;          // 128 samples * 64 h-pairs
                int s = idx >> 6, p = idx & 63; // h = 2p, 2p+1
                float m0 = xs[s * 4 + mi0], m1 = xs[s * 4 + mi1], m2 = cs[s];
                int h0 = 2 * p;
                float r0 = fmaf(sW1[h0 * 3], m0,
                           fmaf(sW1[h0 * 3 + 1], m1,
                           fmaf(sW1[h0 * 3 + 2], m2, sb1[h0])));
                float r1 = fmaf(sW1[h0 * 3 + 3], m0,
                           fmaf(sW1[h0 * 3 + 4], m1,
                           fmaf(sW1[h0 * 3 + 5], m2, sb1[h0 + 1])));
                float2 v = make_float2(fmaxf(r0, 0.0f), fmaxf(r1, 0.0f));
                *(float2*)(h1 + (s >> 2) * 516 + (p >> 1) * 16 +
                           (s & 3) * 4 + (p & 1) * 2) = v;
            }
        }
        __syncthreads();

        // ---- GEMM2: h2 = relu(h1 @ W2^T + b2), 4 samples x 8 outs/thread.
        //      LDS.128 loads; per-acc k-order ascending (bitwise identical). ----
        {
            const float* hb = h1 + q * 516;
            const float* wb = sW2 + (g * 8) * 128;
            unsigned long long acc[8][4];
            #pragma unroll
            for (int jj = 0; jj < 8; jj++)
                #pragma unroll
                for (int ss = 0; ss < 4; ss++) acc[jj][ss] = 0ull;

            #pragma unroll 2
            for (int kq = 0; kq < 32; kq++) {     // kq = 4 k-values
                ulonglong2 hv[4];
                #pragma unroll
                for (int ss = 0; ss < 4; ss++)
                    hv[ss] = *(const ulonglong2*)(hb + kq * 16 + ss * 4);
                #pragma unroll
                for (int jj = 0; jj < 8; jj++) {
                    ulonglong2 w = *(const ulonglong2*)(wb + jj * 128 + kq * 4);
                    #pragma unroll
                    for (int ss = 0; ss < 4; ss++) {
                        acc[jj][ss] = fma2(w.x, hv[ss].x, acc[jj][ss]);
                        acc[jj][ss] = fma2(w.y, hv[ss].y, acc[jj][ss]);
                    }
                }
            }
            // epilogue: STS.128 — thread owns j = g*8 .. g*8+7 (two j-quads)
            #pragma unroll
            for (int ss = 0; ss < 4; ss++) {
                float4 v0, v1;
                v0.x = fmaxf(lo32(acc[0][ss]) + hi32(acc[0][ss]) + sb2[g*8+0], 0.f);
                v0.y = fmaxf(lo32(acc[1][ss]) + hi32(acc[1][ss]) + sb2[g*8+1], 0.f);
                v0.z = fmaxf(lo32(acc[2][ss]) + hi32(acc[2][ss]) + sb2[g*8+2], 0.f);
                v0.w = fmaxf(lo32(acc[3][ss]) + hi32(acc[3][ss]) + sb2[g*8+3], 0.f);
                v1.x = fmaxf(lo32(acc[4][ss]) + hi32(acc[4][ss]) + sb2[g*8+4], 0.f);
                v1.y = fmaxf(lo32(acc[5][ss]) + hi32(acc[5][ss]) + sb2[g*8+5], 0.f);
                v1.z = fmaxf(lo32(acc[6][ss]) + hi32(acc[6][ss]) + sb2[g*8+6], 0.f);
                v1.w = fmaxf(lo32(acc[7][ss]) + hi32(acc[7][ss]) + sb2[g*8+7], 0.f);
                *(float4*)(h2 + q * 516 + (g * 2) * 16 + ss * 4) = v0;
                *(float4*)(h2 + q * 516 + (g * 2 + 1) * 16 + ss * 4) = v1;
            }
        }
        __syncthreads();

        // ---- GEMM3: params = h2 @ W3^T + b3 (48 outs, rows 46/47 zero),
        //      4 samples x 3 outs / thread. Writes pb (aliases h1). ----
        {
            const float* hb = h2 + q * 516;
            const float* wb = sW3 + (g * 3) * 128;
            unsigned long long acc[3][4];
            #pragma unroll
            for (int jj = 0; jj < 3; jj++)
                #pragma unroll
                for (int ss = 0; ss < 4; ss++) acc[jj][ss] = 0ull;

            #pragma unroll 2
            for (int kq = 0; kq < 32; kq++) {
                ulonglong2 hv[4];
                #pragma unroll
                for (int ss = 0; ss < 4; ss++)
                    hv[ss] = *(const ulonglong2*)(hb + kq * 16 + ss * 4);
                #pragma unroll
                for (int jj = 0; jj < 3; jj++) {
                    ulonglong2 w = *(const ulonglong2*)(wb + jj * 128 + kq * 4);
                    #pragma unroll
                    for (int ss = 0; ss < 4; ss++) {
                        acc[jj][ss] = fma2(w.x, hv[ss].x, acc[jj][ss]);
                        acc[jj][ss] = fma2(w.y, hv[ss].y, acc[jj][ss]);
                    }
                }
            }
            #pragma unroll
            for (int jj = 0; jj < 3; jj++) {
                int j = g * 3 + jj;
                float bb = sb3[j];
                #pragma unroll
                for (int ss = 0; ss < 4; ss++) {
                    pb[(q * 4 + ss) * 50 + j] =
                        lo32(acc[jj][ss]) + hi32(acc[jj][ss]) + bb;
                }
            }
        }
        __syncthreads();

        // ---- RQS spline: one thread per (sample, transformed-dim) ----
        if (t < 256) {
            const int s = t >> 1, f = t & 1;
            const int ii = f ? II1c[l] : II0c[l];
            const float* pp = pb + s * 50 + f;

            float uw[8];
            #pragma unroll
            for (int j = 0; j < 8; j++) uw[j] = pp[2 * j];
            float mw = uw[0];
            #pragma unroll
            for (int j = 1; j < 8; j++) mw = fmaxf(mw, uw[j]);
            float ew[8], swsum = 0.0f;
            #pragma unroll
            for (int j = 0; j < 8; j++) { ew[j] = expf(uw[j] - mw); swsum += ew[j]; }
            float scw = (1.0f - MIN_BW * 8.0f) / swsum;
            float cw[9];
            cw[0] = -TAILB;
            {
                float c = 0.0f;
                #pragma unroll
                for (int j = 0; j < 8; j++) {
                    c += MIN_BW + scw * ew[j];
                    cw[j + 1] = fmaf(2.0f * TAILB, c, -TAILB);
                }
            }
            cw[8] = TAILB;

            float uh[8];
            #pragma unroll
            for (int j = 0; j < 8; j++) uh[j] = pp[2 * (8 + j)];
            float mh = uh[0];
            #pragma unroll
            for (int j = 1; j < 8; j++) mh = fmaxf(mh, uh[j]);
            float eh[8], shsum = 0.0f;
            #pragma unroll
            for (int j = 0; j < 8; j++) { eh[j] = expf(uh[j] - mh); shsum += eh[j]; }
            float sch = (1.0f - MIN_BH * 8.0f) / shsum;
            float ch[9];
            ch[0] = -TAILB;
            {
                float c = 0.0f;
                #pragma unroll
                for (int j = 0; j < 8; j++) {
                    c += MIN_BH + sch * eh[j];
                    ch[j + 1] = fmaf(2.0f * TAILB, c, -TAILB);
                }
            }
            ch[8] = TAILB;

            float dv[9];
            dv[0] = 1.0f; dv[8] = 1.0f;
            #pragma unroll
            for (int j = 0; j < 7; j++)
                dv[j + 1] = MIN_DD + softplusf(pp[2 * (16 + j)]);

            float xv = xs[s * 4 + ii];
            bool inside = (xv >= -TAILB) && (xv <= TAILB);
            float xc = fminf(fmaxf(xv, -TAILB), TAILB);

            int bin = 0;
            #pragma unroll
            for (int i = 1; i < 8; i++) if (xc >= cw[i]) bin = i;

            float icw = cw[0], iw = cw[1] - cw[0];
            float ich = ch[0], ih = ch[1] - ch[0];
            float dk = dv[0], dk1 = dv[1];
            #pragma unroll
            for (int i = 1; i < 8; i++) if (bin == i) {
                icw = cw[i]; iw = cw[i + 1] - cw[i];
                ich = ch[i]; ih = ch[i + 1] - ch[i];
                dk = dv[i]; dk1 = dv[i + 1];
            }

            float th = (xc - icw) / iw;
            float delta = ih / iw;
            float omt = 1.0f - th;
            float tomt = th * omt;
            float num = ih * (delta * th * th + dk * tomt);
            float den = delta + (dk + dk1 - 2.0f * delta) * tomt;
            float y = ich + num / den;
            float dnum = delta * delta *
                         (dk1 * th * th + 2.0f * delta * tomt + dk * omt * omt);
            float ladv = logf(dnum) - 2.0f * logf(den);

            xs[s * 4 + ii] = inside ? y : xv;
            lad[t] = inside ? ladv : 0.0f;
        }
        __syncthreads();
        if (t < 128) ldt[t] += lad[2 * t] + lad[2 * t + 1];
    }

    __syncthreads();
    // outputs: x flattened [B,4] then logdets [B,1]
    out[base * 4 + t] = xs[t];
    if (t < 128) out[(size_t)B * 4 + base + t] = ldt[t];
}

extern "C" void kernel_launch(void* const* d_in, const int* in_sizes, int n_in,
                              void* d_out, int out_size)
{
    const float* inputs = (const float*)d_in[0];
    const float* cond   = (const float*)d_in[1];
    const float* W1     = (const float*)d_in[2];
    const float* b1     = (const float*)d_in[3];
    const float* W2     = (const float*)d_in[4];
    const float* b2     = (const float*)d_in[5];
    const float* W3     = (const float*)d_in[6];
    const float* b3     = (const float*)d_in[7];
    float* out = (float*)d_out;

    const int B = in_sizes[0] / 4;
    const int smem_bytes = SMEM_FLOATS * 4;  // 229,056 bytes
    cudaFuncSetAttribute(rqs_fused_kernel,
                         cudaFuncAttributeMaxDynamicSharedMemorySize, smem_bytes);
    rqs_fused_kernel<<<B / 128, 512, smem_bytes>>>(inputs, cond, W1, b1, W2, b2,
                                                   W3, b3, out, B);
}

// round 13
// speedup vs baseline: 1.0398x; 1.0398x over previous
#include <cuda_runtime.h>

#define TAILB 12.0f
#define MIN_BW 1e-6f
#define MIN_BH 1e-6f
#define MIN_DD 1e-6f

// layer index tables
__device__ __constant__ int MI0c[4] = {0, 1, 0, 2};
__device__ __constant__ int MI1c[4] = {2, 3, 1, 3};
__device__ __constant__ int II0c[4] = {1, 0, 2, 0};
__device__ __constant__ int II1c[4] = {3, 2, 3, 1};

// In-place packed fma: acc = a*b + acc. "+l" ties output to the accumulator
// register pair — no copy can be generated around it.
__device__ __forceinline__ void fma2ip(unsigned long long& acc,
                                       unsigned long long a,
                                       unsigned long long b) {
    asm("fma.rn.f32x2 %0, %1, %2, %0;" : "+l"(acc) : "l"(a), "l"(b));
}
__device__ __forceinline__ float lo32(unsigned long long a) {
    return __uint_as_float((unsigned)(a & 0xffffffffull));
}
__device__ __forceinline__ float hi32(unsigned long long a) {
    return __uint_as_float((unsigned)(a >> 32));
}
__device__ __forceinline__ float softplusf(float x) {
    return fmaxf(x, 0.0f) + log1pf(expf(-fabsf(x)));
}

// Shared memory (floats). 128 samples / block, 512 threads.
// h layout (4-k-contiguous, LDS.128): 32 rows of 4 samples, row stride 516.
// Element (s, k): h[(s>>2)*516 + (k>>2)*16 + (s&3)*4 + (k&3)].
// pb (spline params, stride 50 => conflict-free spline reads) ALIASES h1.
#define OFF_H1   0        // 32*516 = 16512
#define OFF_PB   0        // aliases h1 (128*50 = 6400 <= 16512)
#define OFF_H2   16512    // 16512
#define OFF_W2   33024    // 16384
#define OFF_W3   49408    // 48*128 = 6144
#define OFF_W1   55552    // 384
#define OFF_B1   55936    // 128
#define OFF_B2   56064    // 128
#define OFF_B3   56192    // 48
#define OFF_XS   56240    // 512
#define OFF_CS   56752    // 128
#define OFF_LAD  56880    // 256
#define OFF_LDT  57136    // 128
#define SMEM_FLOATS 57264 // 229,056 bytes

__global__ __launch_bounds__(512, 1)
void rqs_fused_kernel(const float* __restrict__ inputs,
                      const float* __restrict__ cond,
                      const float* __restrict__ W1, const float* __restrict__ b1,
                      const float* __restrict__ W2, const float* __restrict__ b2,
                      const float* __restrict__ W3, const float* __restrict__ b3,
                      float* __restrict__ out, int B)
{
    extern __shared__ float sm[];
    float* h1  = sm + OFF_H1;
    float* h2  = sm + OFF_H2;
    float* sW2 = sm + OFF_W2;
    float* sW3 = sm + OFF_W3;
    float* sW1 = sm + OFF_W1;
    float* sb1 = sm + OFF_B1;
    float* sb2 = sm + OFF_B2;
    float* sb3 = sm + OFF_B3;
    float* xs  = sm + OFF_XS;
    float* cs  = sm + OFF_CS;
    float* pb  = sm + OFF_PB;
    float* lad = sm + OFF_LAD;
    float* ldt = sm + OFF_LDT;

    const int t = threadIdx.x;
    const int base = blockIdx.x * 128;

    xs[t] = inputs[base * 4 + t];
    if (t < 128) { cs[t] = cond[base + t]; ldt[t] = 0.0f; }

    const int q  = t & 31;   // sample row: samples 4q .. 4q+3
    const int g  = t >> 5;   // output group 0..15 (uniform per warp)

    #pragma unroll 1
    for (int l = 0; l < 4; l++) {
        __syncthreads();
        // ---- stage layer weights into smem ----
        {
            const float4* w2p = (const float4*)(W2 + l * 16384);
            float4* dW2 = (float4*)sW2;
            #pragma unroll
            for (int i = 0; i < 8; i++) dW2[t + i * 512] = w2p[t + i * 512];

            const float4* w3p = (const float4*)(W3 + l * 5888);
            float4* dW3 = (float4*)sW3;
            #pragma unroll
            for (int i = 0; i < 3; i++) {
                int idx = t + i * 512;
                if (idx < 1472) dW3[idx] = w3p[idx];
            }
            if (t < 64) dW3[1472 + t] = make_float4(0.f, 0.f, 0.f, 0.f);

            if (t < 96) ((float4*)sW1)[t] = ((const float4*)(W1 + l * 384))[t];
            if (t < 128) { sb1[t] = b1[l * 128 + t]; sb2[t] = b2[l * 128 + t]; }
            if (t < 48) sb3[t] = (t < 46) ? b3[l * 46 + t] : 0.0f;
        }
        __syncthreads();

        // ---- layer 1: h1 = relu([x_m0, x_m1, cond] @ W1^T + b1) ----
        {
            const int mi0 = MI0c[l], mi1 = MI1c[l];
            #pragma unroll
            for (int i = 0; i < 16; i++) {
                int idx = t + i * 512;          // 128 samples * 64 h-pairs
                int s = idx >> 6, p = idx & 63; // h = 2p, 2p+1
                float m0 = xs[s * 4 + mi0], m1 = xs[s * 4 + mi1], m2 = cs[s];
                int h0 = 2 * p;
                float r0 = fmaf(sW1[h0 * 3], m0,
                           fmaf(sW1[h0 * 3 + 1], m1,
                           fmaf(sW1[h0 * 3 + 2], m2, sb1[h0])));
                float r1 = fmaf(sW1[h0 * 3 + 3], m0,
                           fmaf(sW1[h0 * 3 + 4], m1,
                           fmaf(sW1[h0 * 3 + 5], m2, sb1[h0 + 1])));
                float2 v = make_float2(fmaxf(r0, 0.0f), fmaxf(r1, 0.0f));
                *(float2*)(h1 + (s >> 2) * 516 + (p >> 1) * 16 +
                           (s & 3) * 4 + (p & 1) * 2) = v;
            }
        }
        __syncthreads();

        // ---- GEMM2: h2 = relu(h1 @ W2^T + b2), 4 samples x 8 outs/thread.
        //      FULLY UNROLLED k loop: all LDS offsets are immediates, zero
        //      address arithmetic in the hot path. In-place fma2 (no MOVs).
        //      Per-acc k-order ascending (bitwise identical). ----
        {
            const float* hb = h1 + q * 516;
            const float* wb = sW2 + (g * 8) * 128;
            unsigned long long acc[8][4];
            #pragma unroll
            for (int jj = 0; jj < 8; jj++)
                #pragma unroll
                for (int ss = 0; ss < 4; ss++) acc[jj][ss] = 0ull;

            #pragma unroll
            for (int kq = 0; kq < 32; kq++) {     // kq = 4 k-values
                ulonglong2 hv[4];
                #pragma unroll
                for (int ss = 0; ss < 4; ss++)
                    hv[ss] = *(const ulonglong2*)(hb + kq * 16 + ss * 4);
                #pragma unroll
                for (int jj = 0; jj < 8; jj++) {
                    ulonglong2 w = *(const ulonglong2*)(wb + jj * 128 + kq * 4);
                    #pragma unroll
                    for (int ss = 0; ss < 4; ss++) {
                        fma2ip(acc[jj][ss], w.x, hv[ss].x);
                        fma2ip(acc[jj][ss], w.y, hv[ss].y);
                    }
                }
            }
            // epilogue: STS.128 — thread owns j = g*8 .. g*8+7 (two j-quads)
            #pragma unroll
            for (int ss = 0; ss < 4; ss++) {
                float4 v0, v1;
                v0.x = fmaxf(lo32(acc[0][ss]) + hi32(acc[0][ss]) + sb2[g*8+0], 0.f);
                v0.y = fmaxf(lo32(acc[1][ss]) + hi32(acc[1][ss]) + sb2[g*8+1], 0.f);
                v0.z = fmaxf(lo32(acc[2][ss]) + hi32(acc[2][ss]) + sb2[g*8+2], 0.f);
                v0.w = fmaxf(lo32(acc[3][ss]) + hi32(acc[3][ss]) + sb2[g*8+3], 0.f);
                v1.x = fmaxf(lo32(acc[4][ss]) + hi32(acc[4][ss]) + sb2[g*8+4], 0.f);
                v1.y = fmaxf(lo32(acc[5][ss]) + hi32(acc[5][ss]) + sb2[g*8+5], 0.f);
                v1.z = fmaxf(lo32(acc[6][ss]) + hi32(acc[6][ss]) + sb2[g*8+6], 0.f);
                v1.w = fmaxf(lo32(acc[7][ss]) + hi32(acc[7][ss]) + sb2[g*8+7], 0.f);
                *(float4*)(h2 + q * 516 + (g * 2) * 16 + ss * 4) = v0;
                *(float4*)(h2 + q * 516 + (g * 2 + 1) * 16 + ss * 4) = v1;
            }
        }
        __syncthreads();

        // ---- GEMM3: params = h2 @ W3^T + b3 (48 outs, rows 46/47 zero),
        //      4 samples x 3 outs / thread. Fully unrolled. Writes pb. ----
        {
            const float* hb = h2 + q * 516;
            const float* wb = sW3 + (g * 3) * 128;
            unsigned long long acc[3][4];
            #pragma unroll
            for (int jj = 0; jj < 3; jj++)
                #pragma unroll
                for (int ss = 0; ss < 4; ss++) acc[jj][ss] = 0ull;

            #pragma unroll
            for (int kq = 0; kq < 32; kq++) {
                ulonglong2 hv[4];
                #pragma unroll
                for (int ss = 0; ss < 4; ss++)
                    hv[ss] = *(const ulonglong2*)(hb + kq * 16 + ss * 4);
                #pragma unroll
                for (int jj = 0; jj < 3; jj++) {
                    ulonglong2 w = *(const ulonglong2*)(wb + jj * 128 + kq * 4);
                    #pragma unroll
                    for (int ss = 0; ss < 4; ss++) {
                        fma2ip(acc[jj][ss], w.x, hv[ss].x);
                        fma2ip(acc[jj][ss], w.y, hv[ss].y);
                    }
                }
            }
            #pragma unroll
            for (int jj = 0; jj < 3; jj++) {
                int j = g * 3 + jj;
                float bb = sb3[j];
                #pragma unroll
                for (int ss = 0; ss < 4; ss++) {
                    pb[(q * 4 + ss) * 50 + j] =
                        lo32(acc[jj][ss]) + hi32(acc[jj][ss]) + bb;
                }
            }
        }
        __syncthreads();

        // ---- RQS spline: one thread per (sample, transformed-dim) ----
        if (t < 256) {
            const int s = t >> 1, f = t & 1;
            const int ii = f ? II1c[l] : II0c[l];
            const float* pp = pb + s * 50 + f;

            float uw[8];
            #pragma unroll
            for (int j = 0; j < 8; j++) uw[j] = pp[2 * j];
            float mw = uw[0];
            #pragma unroll
            for (int j = 1; j < 8; j++) mw = fmaxf(mw, uw[j]);
            float ew[8], swsum = 0.0f;
            #pragma unroll
            for (int j = 0; j < 8; j++) { ew[j] = expf(uw[j] - mw); swsum += ew[j]; }
            float scw = (1.0f - MIN_BW * 8.0f) / swsum;
            float cw[9];
            cw[0] = -TAILB;
            {
                float c = 0.0f;
                #pragma unroll
                for (int j = 0; j < 8; j++) {
                    c += MIN_BW + scw * ew[j];
                    cw[j + 1] = fmaf(2.0f * TAILB, c, -TAILB);
                }
            }
            cw[8] = TAILB;

            float uh[8];
            #pragma unroll
            for (int j = 0; j < 8; j++) uh[j] = pp[2 * (8 + j)];
            float mh = uh[0];
            #pragma unroll
            for (int j = 1; j < 8; j++) mh = fmaxf(mh, uh[j]);
            float eh[8], shsum = 0.0f;
            #pragma unroll
            for (int j = 0; j < 8; j++) { eh[j] = expf(uh[j] - mh); shsum += eh[j]; }
            float sch = (1.0f - MIN_BH * 8.0f) / shsum;
            float ch[9];
            ch[0] = -TAILB;
            {
                float c = 0.0f;
                #pragma unroll
                for (int j = 0; j < 8; j++) {
                    c += MIN_BH + sch * eh[j];
                    ch[j + 1] = fmaf(2.0f * TAILB, c, -TAILB);
                }
            }
            ch[8] = TAILB;

            float dv[9];
            dv[0] = 1.0f; dv[8] = 1.0f;
            #pragma unroll
            for (int j = 0; j < 7; j++)
                dv[j + 1] = MIN_DD + softplusf(pp[2 * (16 + j)]);

            float xv = xs[s * 4 + ii];
            bool inside = (xv >= -TAILB) && (xv <= TAILB);
            float xc = fminf(fmaxf(xv, -TAILB), TAILB);

            int bin = 0;
            #pragma unroll
            for (int i = 1; i < 8; i++) if (xc >= cw[i]) bin = i;

            float icw = cw[0], iw = cw[1] - cw[0];
            float ich = ch[0], ih = ch[1] - ch[0];
            float dk = dv[0], dk1 = dv[1];
            #pragma unroll
            for (int i = 1; i < 8; i++) if (bin == i) {
                icw = cw[i]; iw = cw[i + 1] - cw[i];
                ich = ch[i]; ih = ch[i + 1] - ch[i];
                dk = dv[i]; dk1 = dv[i + 1];
            }

            float th = (xc - icw) / iw;
            float delta = ih / iw;
            float omt = 1.0f - th;
            float tomt = th * omt;
            float num = ih * (delta * th * th + dk * tomt);
            float den = delta + (dk + dk1 - 2.0f * delta) * tomt;
            float y = ich + num / den;
            float dnum = delta * delta *
                         (dk1 * th * th + 2.0f * delta * tomt + dk * omt * omt);
            float ladv = logf(dnum) - 2.0f * logf(den);

            xs[s * 4 + ii] = inside ? y : xv;
            lad[t] = inside ? ladv : 0.0f;
        }
        __syncthreads();
        if (t < 128) ldt[t] += lad[2 * t] + lad[2 * t + 1];
    }

    __syncthreads();
    // outputs: x flattened [B,4] then logdets [B,1]
    out[base * 4 + t] = xs[t];
    if (t < 128) out[(size_t)B * 4 + base + t] = ldt[t];
}

extern "C" void kernel_launch(void* const* d_in, const int* in_sizes, int n_in,
                              void* d_out, int out_size)
{
    const float* inputs = (const float*)d_in[0];
    const float* cond   = (const float*)d_in[1];
    const float* W1     = (const float*)d_in[2];
    const float* b1     = (const float*)d_in[3];
    const float* W2     = (const float*)d_in[4];
    const float* b2     = (const float*)d_in[5];
    const float* W3     = (const float*)d_in[6];
    const float* b3     = (const float*)d_in[7];
    float* out = (float*)d_out;

    const int B = in_sizes[0] / 4;
    const int smem_bytes = SMEM_FLOATS * 4;  // 229,056 bytes
    cudaFuncSetAttribute(rqs_fused_kernel,
                         cudaFuncAttributeMaxDynamicSharedMemorySize, smem_bytes);
    rqs_fused_kernel<<<B / 128, 512, smem_bytes>>>(inputs, cond, W1, b1, W2, b2,
                                                   W3, b3, out, B);
}

// round 16
// speedup vs baseline: 1.0415x; 1.0017x over previous
#include <cuda_runtime.h>

#define TAILB 12.0f
#define MIN_BW 1e-6f
#define MIN_BH 1e-6f
#define MIN_DD 1e-6f

// layer index tables
__device__ __constant__ int MI0c[4] = {0, 1, 0, 2};
__device__ __constant__ int MI1c[4] = {2, 3, 1, 3};
__device__ __constant__ int II0c[4] = {1, 0, 2, 0};
__device__ __constant__ int II1c[4] = {3, 2, 3, 1};

// In-place packed fma: acc = a*b + acc. "+l" ties output to the accumulator
// register pair — no copy can be generated around it.
__device__ __forceinline__ void fma2ip(unsigned long long& acc,
                                       unsigned long long a,
                                       unsigned long long b) {
    asm("fma.rn.f32x2 %0, %1, %2, %0;" : "+l"(acc) : "l"(a), "l"(b));
}
__device__ __forceinline__ float lo32(unsigned long long a) {
    return __uint_as_float((unsigned)(a & 0xffffffffull));
}
__device__ __forceinline__ float hi32(unsigned long long a) {
    return __uint_as_float((unsigned)(a >> 32));
}
__device__ __forceinline__ float softplusf(float x) {
    return fmaxf(x, 0.0f) + log1pf(expf(-fabsf(x)));
}

// Shared memory (floats). 128 samples / block, 512 threads.
// h layout (4-k-contiguous, LDS.128): 32 rows of 4 samples, row stride 516.
// Element (s, k): h[(s>>2)*516 + (k>>2)*16 + (s&3)*4 + (k&3)].
// pb (spline params, stride 50 => conflict-free spline reads) ALIASES h1.
#define OFF_H1   0        // 32*516 = 16512
#define OFF_PB   0        // aliases h1 (128*50 = 6400 <= 16512)
#define OFF_H2   16512    // 16512
#define OFF_W2   33024    // 16384
#define OFF_W3   49408    // 48*128 = 6144
#define OFF_W1   55552    // 384
#define OFF_B1   55936    // 128
#define OFF_B2   56064    // 128
#define OFF_B3   56192    // 48
#define OFF_XS   56240    // 512
#define OFF_CS   56752    // 128
#define OFF_LAD  56880    // 256
#define OFF_LDT  57136    // 128
#define SMEM_FLOATS 57264 // 229,056 bytes

__global__ __launch_bounds__(512, 1)
void rqs_fused_kernel(const float* __restrict__ inputs,
                      const float* __restrict__ cond,
                      const float* __restrict__ W1, const float* __restrict__ b1,
                      const float* __restrict__ W2, const float* __restrict__ b2,
                      const float* __restrict__ W3, const float* __restrict__ b3,
                      float* __restrict__ out, int B)
{
    extern __shared__ float sm[];
    float* h1  = sm + OFF_H1;
    float* h2  = sm + OFF_H2;
    float* sW2 = sm + OFF_W2;
    float* sW3 = sm + OFF_W3;
    float* sW1 = sm + OFF_W1;
    float* sb1 = sm + OFF_B1;
    float* sb2 = sm + OFF_B2;
    float* sb3 = sm + OFF_B3;
    float* xs  = sm + OFF_XS;
    float* cs  = sm + OFF_CS;
    float* pb  = sm + OFF_PB;
    float* lad = sm + OFF_LAD;
    float* ldt = sm + OFF_LDT;

    const int t = threadIdx.x;
    const int base = blockIdx.x * 128;

    xs[t] = inputs[base * 4 + t];
    if (t < 128) { cs[t] = cond[base + t]; ldt[t] = 0.0f; }

    const int q  = t & 31;   // sample row: samples 4q .. 4q+3
    const int g  = t >> 5;   // output group 0..15 (uniform per warp)

    #pragma unroll 1
    for (int l = 0; l < 4; l++) {
        __syncthreads();
        // ---- stage layer weights into smem ----
        {
            const float4* w2p = (const float4*)(W2 + l * 16384);
            float4* dW2 = (float4*)sW2;
            #pragma unroll
            for (int i = 0; i < 8; i++) dW2[t + i * 512] = w2p[t + i * 512];

            const float4* w3p = (const float4*)(W3 + l * 5888);
            float4* dW3 = (float4*)sW3;
            #pragma unroll
            for (int i = 0; i < 3; i++) {
                int idx = t + i * 512;
                if (idx < 1472) dW3[idx] = w3p[idx];
            }
            if (t < 64) dW3[1472 + t] = make_float4(0.f, 0.f, 0.f, 0.f);

            if (t < 96) ((float4*)sW1)[t] = ((const float4*)(W1 + l * 384))[t];
            if (t < 128) { sb1[t] = b1[l * 128 + t]; sb2[t] = b2[l * 128 + t]; }
            if (t < 48) sb3[t] = (t < 46) ? b3[l * 46 + t] : 0.0f;
        }
        __syncthreads();

        // ---- layer 1: h1 = relu([x_m0, x_m1, cond] @ W1^T + b1) ----
        {
            const int mi0 = MI0c[l], mi1 = MI1c[l];
            #pragma unroll
            for (int i = 0; i < 16; i++) {
                int idx = t + i * 512;          // 128 samples * 64 h-pairs
                int s = idx >> 6, p = idx & 63; // h = 2p, 2p+1
                float m0 = xs[s * 4 + mi0], m1 = xs[s * 4 + mi1], m2 = cs[s];
                int h0 = 2 * p;
                float r0 = fmaf(sW1[h0 * 3], m0,
                           fmaf(sW1[h0 * 3 + 1], m1,
                           fmaf(sW1[h0 * 3 + 2], m2, sb1[h0])));
                float r1 = fmaf(sW1[h0 * 3 + 3], m0,
                           fmaf(sW1[h0 * 3 + 4], m1,
                           fmaf(sW1[h0 * 3 + 5], m2, sb1[h0 + 1])));
                float2 v = make_float2(fmaxf(r0, 0.0f), fmaxf(r1, 0.0f));
                *(float2*)(h1 + (s >> 2) * 516 + (p >> 1) * 16 +
                           (s & 3) * 4 + (p & 1) * 2) = v;
            }
        }
        __syncthreads();

        // ---- GEMM2: h2 = relu(h1 @ W2^T + b2), 4 samples x 8 outs/thread.
        //      jj-INNERMOST ordering: the hv operand is held fixed across
        //      runs of 8 consecutive fma2 (operand-reuse friendly; 8
        //      independent acc chains, no RAW stalls). Per-acc k-order is
        //      still x-then-y ascending kq => bitwise identical. ----
        {
            const float* hb = h1 + q * 516;
            const float* wb = sW2 + (g * 8) * 128;
            unsigned long long acc[8][4];
            #pragma unroll
            for (int jj = 0; jj < 8; jj++)
                #pragma unroll
                for (int ss = 0; ss < 4; ss++) acc[jj][ss] = 0ull;

            #pragma unroll
            for (int kq = 0; kq < 32; kq++) {     // kq = 4 k-values
                ulonglong2 w[8];
                #pragma unroll
                for (int jj = 0; jj < 8; jj++)
                    w[jj] = *(const ulonglong2*)(wb + jj * 128 + kq * 4);
                #pragma unroll
                for (int ss = 0; ss < 4; ss++) {
                    ulonglong2 hv = *(const ulonglong2*)(hb + kq * 16 + ss * 4);
                    #pragma unroll
                    for (int jj = 0; jj < 8; jj++)
                        fma2ip(acc[jj][ss], w[jj].x, hv.x);
                    #pragma unroll
                    for (int jj = 0; jj < 8; jj++)
                        fma2ip(acc[jj][ss], w[jj].y, hv.y);
                }
            }
            // epilogue: STS.128 — thread owns j = g*8 .. g*8+7 (two j-quads)
            #pragma unroll
            for (int ss = 0; ss < 4; ss++) {
                float4 v0, v1;
                v0.x = fmaxf(lo32(acc[0][ss]) + hi32(acc[0][ss]) + sb2[g*8+0], 0.f);
                v0.y = fmaxf(lo32(acc[1][ss]) + hi32(acc[1][ss]) + sb2[g*8+1], 0.f);
                v0.z = fmaxf(lo32(acc[2][ss]) + hi32(acc[2][ss]) + sb2[g*8+2], 0.f);
                v0.w = fmaxf(lo32(acc[3][ss]) + hi32(acc[3][ss]) + sb2[g*8+3], 0.f);
                v1.x = fmaxf(lo32(acc[4][ss]) + hi32(acc[4][ss]) + sb2[g*8+4], 0.f);
                v1.y = fmaxf(lo32(acc[5][ss]) + hi32(acc[5][ss]) + sb2[g*8+5], 0.f);
                v1.z = fmaxf(lo32(acc[6][ss]) + hi32(acc[6][ss]) + sb2[g*8+6], 0.f);
                v1.w = fmaxf(lo32(acc[7][ss]) + hi32(acc[7][ss]) + sb2[g*8+7], 0.f);
                *(float4*)(h2 + q * 516 + (g * 2) * 16 + ss * 4) = v0;
                *(float4*)(h2 + q * 516 + (g * 2 + 1) * 16 + ss * 4) = v1;
            }
        }
        __syncthreads();

        // ---- GEMM3: params = h2 @ W3^T + b3 (48 outs, rows 46/47 zero),
        //      4 samples x 3 outs / thread, jj-innermost. Writes pb. ----
        {
            const float* hb = h2 + q * 516;
            const float* wb = sW3 + (g * 3) * 128;
            unsigned long long acc[3][4];
            #pragma unroll
            for (int jj = 0; jj < 3; jj++)
                #pragma unroll
                for (int ss = 0; ss < 4; ss++) acc[jj][ss] = 0ull;

            #pragma unroll
            for (int kq = 0; kq < 32; kq++) {
                ulonglong2 w[3];
                #pragma unroll
                for (int jj = 0; jj < 3; jj++)
                    w[jj] = *(const ulonglong2*)(wb + jj * 128 + kq * 4);
                #pragma unroll
                for (int ss = 0; ss < 4; ss++) {
                    ulonglong2 hv = *(const ulonglong2*)(hb + kq * 16 + ss * 4);
                    #pragma unroll
                    for (int jj = 0; jj < 3; jj++)
                        fma2ip(acc[jj][ss], w[jj].x, hv.x);
                    #pragma unroll
                    for (int jj = 0; jj < 3; jj++)
                        fma2ip(acc[jj][ss], w[jj].y, hv.y);
                }
            }
            #pragma unroll
            for (int jj = 0; jj < 3; jj++) {
                int j = g * 3 + jj;
                float bb = sb3[j];
                #pragma unroll
                for (int ss = 0; ss < 4; ss++) {
                    pb[(q * 4 + ss) * 50 + j] =
                        lo32(acc[jj][ss]) + hi32(acc[jj][ss]) + bb;
                }
            }
        }
        __syncthreads();

        // ---- RQS spline: one thread per (sample, transformed-dim) ----
        if (t < 256) {
            const int s = t >> 1, f = t & 1;
            const int ii = f ? II1c[l] : II0c[l];
            const float* pp = pb + s * 50 + f;

            float uw[8];
            #pragma unroll
            for (int j = 0; j < 8; j++) uw[j] = pp[2 * j];
            float mw = uw[0];
            #pragma unroll
            for (int j = 1; j < 8; j++) mw = fmaxf(mw, uw[j]);
            float ew[8], swsum = 0.0f;
            #pragma unroll
            for (int j = 0; j < 8; j++) { ew[j] = expf(uw[j] - mw); swsum += ew[j]; }
            float scw = (1.0f - MIN_BW * 8.0f) / swsum;
            float cw[9];
            cw[0] = -TAILB;
            {
                float c = 0.0f;
                #pragma unroll
                for (int j = 0; j < 8; j++) {
                    c += MIN_BW + scw * ew[j];
                    cw[j + 1] = fmaf(2.0f * TAILB, c, -TAILB);
                }
            }
            cw[8] = TAILB;

            float uh[8];
            #pragma unroll
            for (int j = 0; j < 8; j++) uh[j] = pp[2 * (8 + j)];
            float mh = uh[0];
            #pragma unroll
            for (int j = 1; j < 8; j++) mh = fmaxf(mh, uh[j]);
            float eh[8], shsum = 0.0f;
            #pragma unroll
            for (int j = 0; j < 8; j++) { eh[j] = expf(uh[j] - mh); shsum += eh[j]; }
            float sch = (1.0f - MIN_BH * 8.0f) / shsum;
            float ch[9];
            ch[0] = -TAILB;
            {
                float c = 0.0f;
                #pragma unroll
                for (int j = 0; j < 8; j++) {
                    c += MIN_BH + sch * eh[j];
                    ch[j + 1] = fmaf(2.0f * TAILB, c, -TAILB);
                }
            }
            ch[8] = TAILB;

            float dv[9];
            dv[0] = 1.0f; dv[8] = 1.0f;
            #pragma unroll
            for (int j = 0; j < 7; j++)
                dv[j + 1] = MIN_DD + softplusf(pp[2 * (16 + j)]);

            float xv = xs[s * 4 + ii];
            bool inside = (xv >= -TAILB) && (xv <= TAILB);
            float xc = fminf(fmaxf(xv, -TAILB), TAILB);

            int bin = 0;
            #pragma unroll
            for (int i = 1; i < 8; i++) if (xc >= cw[i]) bin = i;

            float icw = cw[0], iw = cw[1] - cw[0];
            float ich = ch[0], ih = ch[1] - ch[0];
            float dk = dv[0], dk1 = dv[1];
            #pragma unroll
            for (int i = 1; i < 8; i++) if (bin == i) {
                icw = cw[i]; iw = cw[i + 1] - cw[i];
                ich = ch[i]; ih = ch[i + 1] - ch[i];
                dk = dv[i]; dk1 = dv[i + 1];
            }

            float th = (xc - icw) / iw;
            float delta = ih / iw;
            float omt = 1.0f - th;
            float tomt = th * omt;
            float num = ih * (delta * th * th + dk * tomt);
            float den = delta + (dk + dk1 - 2.0f * delta) * tomt;
            float y = ich + num / den;
            float dnum = delta * delta *
                         (dk1 * th * th + 2.0f * delta * tomt + dk * omt * omt);
            float ladv = logf(dnum) - 2.0f * logf(den);

            xs[s * 4 + ii] = inside ? y : xv;
            lad[t] = inside ? ladv : 0.0f;
        }
        __syncthreads();
        if (t < 128) ldt[t] += lad[2 * t] + lad[2 * t + 1];
    }

    __syncthreads();
    // outputs: x flattened [B,4] then logdets [B,1]
    out[base * 4 + t] = xs[t];
    if (t < 128) out[(size_t)B * 4 + base + t] = ldt[t];
}

extern "C" void kernel_launch(void* const* d_in, const int* in_sizes, int n_in,
                              void* d_out, int out_size)
{
    const float* inputs = (const float*)d_in[0];
    const float* cond   = (const float*)d_in[1];
    const float* W1     = (const float*)d_in[2];
    const float* b1     = (const float*)d_in[3];
    const float* W2     = (const float*)d_in[4];
    const float* b2     = (const float*)d_in[5];
    const float* W3     = (const float*)d_in[6];
    const float* b3     = (const float*)d_in[7];
    float* out = (float*)d_out;

    const int B = in_sizes[0] / 4;
    const int smem_bytes = SMEM_FLOATS * 4;  // 229,056 bytes
    cudaFuncSetAttribute(rqs_fused_kernel,
                         cudaFuncAttributeMaxDynamicSharedMemorySize, smem_bytes);
    rqs_fused_kernel<<<B / 128, 512, smem_bytes>>>(inputs, cond, W1, b1, W2, b2,
                                                   W3, b3, out, B);
}